// round 7
// baseline (speedup 1.0000x reference)
#include <cuda_runtime.h>
#include <cuda_bf16.h>
#include <cstdint>
#include <cstddef>

#define NNODES 3000
#define NFEAT 2
#define NUNITS 64
#define BATCH 16
#define CCH (NFEAT + NUNITS)
#define NCOLS (CCH * BATCH)        // 1056
#define NGATE (2 * NUNITS)         // 128
#define HXSZ (NNODES * NUNITS)

#define KPAD 3008
#define MPAD 1152
#define NPADS 3072
#define NCHUNK 47
#define MT 128
#define NT 256

#define KP 352                     // 11*32, proj K
#define NCHUNK_P 11
#define NBLK_P 375                 // 3000/8

#if defined(__CUDA_ARCH_FEAT_SM103_ALL) || defined(__CUDA_ARCH_FEAT_SM100_ALL) || \
    (defined(__CUDA_ARCH_SPECIFIC__) && (__CUDA_ARCH_SPECIFIC__ >= 1000))
#define HAS_TCGEN05 1
#else
#define HAS_TCGEN05 0
#endif

#define MMA_IDESC ((1u<<4)|(1u<<7)|(1u<<10)|((NT/8)<<17)|((MT/16)<<24))
#define IDESC_N128 ((1u<<4)|(1u<<7)|(1u<<10)|(16u<<17)|(8u<<24))
#define IDESC_N64  ((1u<<4)|(1u<<7)|(1u<<10)|(8u<<17)|(8u<<24))

__device__ __nv_bfloat16 g_S0h[(size_t)NPADS * KPAD];
__device__ __nv_bfloat16 g_S0l[(size_t)NPADS * KPAD];
__device__ __nv_bfloat16 g_S1h[(size_t)NPADS * KPAD];
__device__ __nv_bfloat16 g_S1l[(size_t)NPADS * KPAD];
__device__ __nv_bfloat16 g_X0Th[(size_t)MPAD * KPAD];
__device__ __nv_bfloat16 g_X0Tl[(size_t)MPAD * KPAD];
__device__ __nv_bfloat16 g_X1aTh[(size_t)MPAD * KPAD];
__device__ __nv_bfloat16 g_X1aTl[(size_t)MPAD * KPAD];
__device__ __nv_bfloat16 g_X1bTh[(size_t)MPAD * KPAD];
__device__ __nv_bfloat16 g_X1bTl[(size_t)MPAD * KPAD];
__device__ float g_X0[(size_t)NNODES * NCOLS];
__device__ float g_X1a[(size_t)NNODES * NCOLS];
__device__ float g_X2a[(size_t)NNODES * NCOLS];
__device__ float g_X1b[(size_t)NNODES * NCOLS];
__device__ float g_X2b[(size_t)NNODES * NCOLS];
__device__ __nv_bfloat16 g_Wgth[(size_t)NGATE * KP];
__device__ __nv_bfloat16 g_Wgtl[(size_t)NGATE * KP];
__device__ __nv_bfloat16 g_Wcth[(size_t)NUNITS * KP];
__device__ __nv_bfloat16 g_Wctl[(size_t)NUNITS * KP];
__device__ float g_invdr[NNODES];
__device__ float g_dcol[NNODES];
__device__ float g_invdc[NNODES];
__device__ float g_u[(size_t)BATCH * NNODES * NUNITS];

__device__ __forceinline__ uint32_t smem_u32(const void* p) {
    uint32_t a;
    asm("{ .reg .u64 t; cvta.to.shared.u64 t, %1; cvt.u32.u64 %0, t; }" : "=r"(a) : "l"(p));
    return a;
}
static __device__ __forceinline__ uint32_t sw128(uint32_t off) { return off ^ ((off >> 3) & 0x70); }
static __device__ __forceinline__ uint32_t sw64(uint32_t off) { return off ^ ((off >> 3) & 0x30); }
static __device__ __forceinline__ void split_bf16(float v, __nv_bfloat16& h, __nv_bfloat16& l) {
    h = __float2bfloat16(v);
    l = __float2bfloat16(v - __bfloat162float(h));
}

#define CP_ASYNC16(dst, src) \
    asm volatile("cp.async.cg.shared.global [%0], [%1], 16;" :: "r"(dst), "l"(src) : "memory")
#define CP_COMMIT() asm volatile("cp.async.commit_group;" ::: "memory")
#define CP_WAIT1()  asm volatile("cp.async.wait_group 1;" ::: "memory")
#define CP_WAIT0()  asm volatile("cp.async.wait_group 0;" ::: "memory")

#if HAS_TCGEN05
__device__ __forceinline__ uint32_t elect_one() {
    uint32_t pred;
    asm volatile("{\n\t.reg .pred p;\n\telect.sync _|p, 0xFFFFFFFF;\n\tselp.b32 %0, 1, 0, p;\n\t}"
                 : "=r"(pred));
    return pred;
}
#define MBAR_INIT(a, c) asm volatile("mbarrier.init.shared.b64 [%0], %1;" :: "r"(a), "r"(c) : "memory")
#define MBAR_INVAL(a)   asm volatile("mbarrier.inval.shared.b64 [%0];" :: "r"(a) : "memory")
__device__ __forceinline__ void mbar_wait(uint32_t addr, uint32_t parity) {
    uint32_t done;
    asm volatile("{\n\t.reg .pred p;\n\t"
                 "mbarrier.try_wait.parity.acquire.cta.shared::cta.b64 p, [%1], %2;\n\t"
                 "selp.b32 %0, 1, 0, p;\n\t}"
                 : "=r"(done) : "r"(addr), "r"(parity) : "memory");
    if (!done) {
        asm volatile("{\n\t.reg .pred P1;\n\t"
                     "WL_%=:\n\t"
                     "mbarrier.try_wait.parity.acquire.cta.shared::cta.b64 P1, [%0], %1, 0x989680;\n\t"
                     "@P1 bra.uni WD_%=;\n\t"
                     "bra.uni WL_%=;\n\t"
                     "WD_%=:\n\t}"
                     :: "r"(addr), "r"(parity) : "memory");
    }
}
#define TC_ALLOC(sm, n)   asm volatile("tcgen05.alloc.cta_group::1.sync.aligned.shared::cta.b32 [%0], %1;" :: "r"(sm), "r"(n) : "memory")
#define TC_DEALLOC(t, n)  asm volatile("tcgen05.dealloc.cta_group::1.sync.aligned.b32 %0, %1;" :: "r"(t), "r"(n))
#define TC_RELINQ()       asm volatile("tcgen05.relinquish_alloc_permit.cta_group::1.sync.aligned;")
#define TC_COMMIT(mb)     asm volatile("tcgen05.commit.cta_group::1.mbarrier::arrive::one.shared::cluster.b64 [%0];" :: "r"(mb) : "memory")
#define TC_FENCE_AFTER()  asm volatile("tcgen05.fence::after_thread_sync;" ::: "memory")
#define TC_WAIT_LD()      asm volatile("tcgen05.wait::ld.sync.aligned;" ::: "memory")
#define FENCE_ASYNC()     asm volatile("fence.proxy.async.shared::cta;" ::: "memory")

__device__ __forceinline__ void mma_f16_ss(uint32_t d, uint64_t a, uint64_t b,
                                           uint32_t idesc, uint32_t en) {
    asm volatile("{\n\t.reg .pred p;\n\tsetp.ne.u32 p, %4, 0;\n\t"
                 "tcgen05.mma.cta_group::1.kind::f16 [%0], %1, %2, %3, {%5,%5,%5,%5}, p;\n\t}"
                 :: "r"(d), "l"(a), "l"(b), "r"(idesc), "r"(en), "r"(0u) : "memory");
}

#define LDTM_X32(r, addr) \
    asm volatile("tcgen05.ld.sync.aligned.32x32b.x32.b32 " \
        "{%0,%1,%2,%3,%4,%5,%6,%7,%8,%9,%10,%11,%12,%13,%14,%15," \
        "%16,%17,%18,%19,%20,%21,%22,%23,%24,%25,%26,%27,%28,%29,%30,%31}, [%32];" \
        : "=r"((r)[0]),"=r"((r)[1]),"=r"((r)[2]),"=r"((r)[3]),"=r"((r)[4]),"=r"((r)[5]), \
          "=r"((r)[6]),"=r"((r)[7]),"=r"((r)[8]),"=r"((r)[9]),"=r"((r)[10]),"=r"((r)[11]), \
          "=r"((r)[12]),"=r"((r)[13]),"=r"((r)[14]),"=r"((r)[15]),"=r"((r)[16]),"=r"((r)[17]), \
          "=r"((r)[18]),"=r"((r)[19]),"=r"((r)[20]),"=r"((r)[21]),"=r"((r)[22]),"=r"((r)[23]), \
          "=r"((r)[24]),"=r"((r)[25]),"=r"((r)[26]),"=r"((r)[27]),"=r"((r)[28]),"=r"((r)[29]), \
          "=r"((r)[30]),"=r"((r)[31]) : "r"(addr))

static __device__ __forceinline__ uint64_t make_desc(uint32_t addr) {
    const uint64_t base = (uint64_t(2) << 61) | (uint64_t(1) << 46) |
                          (uint64_t(64) << 32) | (uint64_t(1) << 16);
    return base | ((uint64_t)(addr >> 4) & 0x3FFF);
}
static __device__ __forceinline__ uint64_t make_desc64(uint32_t addr) {
    const uint64_t base = (uint64_t(4) << 61) | (uint64_t(1) << 46) |
                          (uint64_t(32) << 32) | (uint64_t(1) << 16);
    return base | ((uint64_t)(addr >> 4) & 0x3FFF);
}
#else
__device__ __forceinline__ void ldm4(uint32_t* r, uint32_t addr) {
    asm volatile("ldmatrix.sync.aligned.m8n8.x4.shared.b16 {%0,%1,%2,%3}, [%4];"
                 : "=r"(r[0]), "=r"(r[1]), "=r"(r[2]), "=r"(r[3]) : "r"(addr));
}
__device__ __forceinline__ void mma16816(float* c, const uint32_t* a, uint32_t b0, uint32_t b1) {
    asm volatile("mma.sync.aligned.m16n8k16.row.col.f32.bf16.bf16.f32 "
                 "{%0,%1,%2,%3}, {%4,%5,%6,%7}, {%8,%9}, {%0,%1,%2,%3};"
                 : "+f"(c[0]), "+f"(c[1]), "+f"(c[2]), "+f"(c[3])
                 : "r"(a[0]), "r"(a[1]), "r"(a[2]), "r"(a[3]), "r"(b0), "r"(b1));
}
#endif

// ---------------- degrees / supports ----------------
__global__ void k_rowsum(const float* __restrict__ A, float* __restrict__ invdr,
                         float* __restrict__ dcol) {
    if (blockIdx.x < 12) {
        int j = blockIdx.x * 256 + threadIdx.x;
        if (j < NNODES) dcol[j] = 0.f;
    }
    __shared__ float red[256];
    int r = blockIdx.x;
    float s = 0.f;
    for (int j = threadIdx.x; j < NNODES; j += 256) s += A[(size_t)r * NNODES + j];
    red[threadIdx.x] = s;
    __syncthreads();
    for (int w = 128; w > 0; w >>= 1) {
        if (threadIdx.x < w) red[threadIdx.x] += red[threadIdx.x + w];
        __syncthreads();
    }
    if (threadIdx.x == 0) {
        float d = red[0];
        invdr[r] = (d > 0.f) ? 1.f / d : 0.f;
    }
}
__global__ void k_colsum_part(const float* __restrict__ A, float* __restrict__ dcol) {
    int j = blockIdx.x * blockDim.x + threadIdx.x;
    if (j >= NNODES) return;
    int r0 = blockIdx.y * 125;
    float s = 0.f;
    for (int r = r0; r < r0 + 125; r++) s += A[(size_t)r * NNODES + j];
    atomicAdd(&dcol[j], s);
}
__global__ void k_buildS0_split(const float* __restrict__ A, const float* __restrict__ invdr,
                                __nv_bfloat16* __restrict__ Sh, __nv_bfloat16* __restrict__ Sl,
                                const float* __restrict__ dcol, float* __restrict__ invdc) {
    int tx = threadIdx.x, ty = threadIdx.y;
    if (blockIdx.x == 0 && blockIdx.y < 12) {
        int j = blockIdx.y * 256 + ty * 32 + tx;
        if (j < NNODES) {
            float d = dcol[j];
            invdc[j] = (d > 0.f) ? 1.f / d : 0.f;
        }
    }
    __shared__ float sm[32][33];
    int i0 = blockIdx.x * 32;
    int j0 = blockIdx.y * 32;
#pragma unroll
    for (int r = 0; r < 4; r++) {
        int j = j0 + ty + r * 8;
        int i = i0 + tx;
        sm[ty + r * 8][tx] = (j < NNODES && i < NNODES) ? A[(size_t)j * NNODES + i] : 0.f;
    }
    __syncthreads();
#pragma unroll
    for (int r = 0; r < 4; r++) {
        int i = i0 + ty + r * 8;
        int j = j0 + tx;
        if (i < NPADS && j < KPAD) {
            float v = (i < NNODES && j < NNODES) ? sm[tx][ty + r * 8] * invdr[j] : 0.f;
            __nv_bfloat16 h, l;
            split_bf16(v, h, l);
            Sh[(size_t)i * KPAD + j] = h;
            Sl[(size_t)i * KPAD + j] = l;
        }
    }
}
__global__ void k_buildS1_split(const float* __restrict__ A, const float* __restrict__ invdc,
                                __nv_bfloat16* __restrict__ Sh, __nv_bfloat16* __restrict__ Sl) {
    int j = blockIdx.x * blockDim.x + threadIdx.x;
    int i = blockIdx.y;
    if (j >= KPAD) return;
    float v = (i < NNODES && j < NNODES) ? A[(size_t)i * NNODES + j] * invdc[j] : 0.f;
    __nv_bfloat16 h, l;
    split_bf16(v, h, l);
    Sh[(size_t)i * KPAD + j] = h;
    Sl[(size_t)i * KPAD + j] = l;
}

// ---------------- X0 builders ----------------
__global__ void k_buildX0(const float* __restrict__ inputs, const float* __restrict__ hx,
                          float* __restrict__ X0) {
    size_t total = (size_t)NNODES * NCOLS;
    for (size_t idx = (size_t)blockIdx.x * blockDim.x + threadIdx.x; idx < total;
         idx += (size_t)gridDim.x * blockDim.x) {
        int n = (int)(idx / NCOLS);
        int r = (int)(idx - (size_t)n * NCOLS);
        int c = r >> 4;
        int b = r & 15;
        float v = (c < NFEAT) ? inputs[(size_t)b * (NNODES * NFEAT) + n * NFEAT + c]
                              : hx[(size_t)b * HXSZ + n * NUNITS + (c - NFEAT)];
        X0[idx] = v;
    }
}
__global__ void k_buildX0T(const float* __restrict__ inputs, const float* __restrict__ hx,
                           __nv_bfloat16* __restrict__ Th, __nv_bfloat16* __restrict__ Tl) {
    size_t total = (size_t)MPAD * KPAD;
    for (size_t idx = (size_t)blockIdx.x * blockDim.x + threadIdx.x; idx < total;
         idx += (size_t)gridDim.x * blockDim.x) {
        int r = (int)(idx / KPAD);
        int n = (int)(idx - (size_t)r * KPAD);
        float v = 0.f;
        if (r < NCOLS && n < NNODES) {
            int c = r >> 4;
            int b = r & 15;
            v = (c < NFEAT) ? inputs[(size_t)b * (NNODES * NFEAT) + n * NFEAT + c]
                            : hx[(size_t)b * HXSZ + n * NUNITS + (c - NFEAT)];
        }
        __nv_bfloat16 h, l;
        split_bf16(v, h, l);
        Th[idx] = h;
        Tl[idx] = l;
    }
}
#define PADELEMS ((MPAD - NCOLS) * KPAD + NCOLS * 8)
__global__ void k_zero_padsT(__nv_bfloat16* a, __nv_bfloat16* b,
                             __nv_bfloat16* c, __nv_bfloat16* d) {
    int idx = blockIdx.x * blockDim.x + threadIdx.x;
    if (idx >= PADELEMS) return;
    size_t off;
    if (idx < (MPAD - NCOLS) * KPAD) {
        int r = NCOLS + idx / KPAD;
        int col = idx % KPAD;
        off = (size_t)r * KPAD + col;
    } else {
        int k = idx - (MPAD - NCOLS) * KPAD;
        int r = k >> 3;
        int col = NNODES + (k & 7);
        off = (size_t)r * KPAD + col;
    }
    __nv_bfloat16 z = __float2bfloat16(0.f);
    a[off] = z; b[off] = z; c[off] = z; d[off] = z;
}

// ---------------- W transpose/split: Wt[o][j], j=(m*66+c), pad to 352 ----------------
__global__ void k_buildWt(const float* __restrict__ W, int width,
                          __nv_bfloat16* __restrict__ Wth, __nv_bfloat16* __restrict__ Wtl) {
    int total = width * KP;
    for (int idx = blockIdx.x * blockDim.x + threadIdx.x; idx < total;
         idx += gridDim.x * blockDim.x) {
        int o = idx / KP;
        int j = idx - o * KP;
        float v = 0.f;
        if (j < 330) {
            int m = j / 66, c = j - m * 66;
            v = W[(size_t)(c * 5 + m) * width + o];
        }
        __nv_bfloat16 h, l;
        split_bf16(v, h, l);
        Wth[idx] = h;
        Wtl[idx] = l;
    }
}

// ---------------- main tensor-core GEMM (R4 config, verbatim) ----------------
#define ST_AH 0
#define ST_AL 16384
#define ST_BH 32768
#define ST_BL 65536
#define STAGE_SZ 98304
#define SMEM_DYN (2 * STAGE_SZ)
#define SST 264

__global__ __launch_bounds__(256, 1)
void k_gemm_tc(const __nv_bfloat16* __restrict__ Ah0, const __nv_bfloat16* __restrict__ Al0,
               const __nv_bfloat16* __restrict__ Ah1, const __nv_bfloat16* __restrict__ Al1,
               const __nv_bfloat16* __restrict__ Bh0, const __nv_bfloat16* __restrict__ Bl0,
               const __nv_bfloat16* __restrict__ Bh1, const __nv_bfloat16* __restrict__ Bl1,
               const float* __restrict__ Xprev,
               float* __restrict__ Yf0, float* __restrict__ Yf1,
               __nv_bfloat16* __restrict__ YTh0, __nv_bfloat16* __restrict__ YTl0,
               __nv_bfloat16* __restrict__ YTh1, __nv_bfloat16* __restrict__ YTl1,
               float alpha, float beta) {
    extern __shared__ __align__(1024) unsigned char dynsm[];
    const int t = threadIdx.x;
    const int m0 = blockIdx.y * MT;
    const int n0 = blockIdx.x * NT;
    const int z = blockIdx.z;
    const uint32_t dyn_u32 = smem_u32(dynsm);

    const __nv_bfloat16* Ahg = (z ? Ah1 : Ah0) + (size_t)m0 * KPAD;
    const __nv_bfloat16* Alg = (z ? Al1 : Al0) + (size_t)m0 * KPAD;
    const __nv_bfloat16* Bhg = (z ? Bh1 : Bh0) + (size_t)n0 * KPAD;
    const __nv_bfloat16* Blg = (z ? Bl1 : Bl0) + (size_t)n0 * KPAD;
    float* Yf = z ? Yf1 : Yf0;
    __nv_bfloat16* YTh = z ? YTh1 : YTh0;
    __nv_bfloat16* YTl = z ? YTl1 : YTl0;

    auto load_chunk = [&](int ck, uint32_t stg) {
        const int kb = ck * 64;
#pragma unroll
        for (int i = 0; i < 4; i++) {
            int idx = t + i * 256;
            int row = idx >> 3, seg = idx & 7;
            size_t go = (size_t)row * KPAD + kb + seg * 8;
            uint32_t so = sw128((uint32_t)(row * 128 + seg * 16));
            CP_ASYNC16(dyn_u32 + stg + ST_AH + so, Ahg + go);
            CP_ASYNC16(dyn_u32 + stg + ST_AL + so, Alg + go);
        }
#pragma unroll
        for (int i = 0; i < 8; i++) {
            int idx = t + i * 256;
            int row = idx >> 3, seg = idx & 7;
            size_t go = (size_t)row * KPAD + kb + seg * 8;
            uint32_t so = sw128((uint32_t)(row * 128 + seg * 16));
            CP_ASYNC16(dyn_u32 + stg + ST_BH + so, Bhg + go);
            CP_ASYNC16(dyn_u32 + stg + ST_BL + so, Blg + go);
        }
        CP_COMMIT();
    };

#if HAS_TCGEN05
    __shared__ uint32_t s_tmem;
    __shared__ __align__(8) uint64_t s_mbar[2];
    const uint32_t mbar0 = smem_u32(&s_mbar[0]);
    const uint32_t mbar1 = smem_u32(&s_mbar[1]);

    if ((t >> 5) == 0) TC_ALLOC(smem_u32(&s_tmem), 256);
    if (t == 0) {
        MBAR_INIT(mbar0, 1);
        MBAR_INIT(mbar1, 1);
    }
    __syncthreads();
    const uint32_t tmem = s_tmem;

    load_chunk(0, 0);
    load_chunk(1, STAGE_SZ);

    for (int k = 0; k < NCHUNK; k++) {
        const int s = k & 1;
        const uint32_t stage = s ? STAGE_SZ : 0;
        if (k == NCHUNK - 1) { CP_WAIT0(); } else { CP_WAIT1(); }
        __syncthreads();
        if ((t >> 5) == 0) {
            FENCE_ASYNC();
            if (elect_one()) {
                uint64_t dAh = make_desc(dyn_u32 + stage + ST_AH);
                uint64_t dAl = make_desc(dyn_u32 + stage + ST_AL);
                uint64_t dBh = make_desc(dyn_u32 + stage + ST_BH);
                uint64_t dBl = make_desc(dyn_u32 + stage + ST_BL);
#pragma unroll
                for (int ks = 0; ks < 4; ks++)
                    mma_f16_ss(tmem, dAh + ks * 2, dBh + ks * 2, MMA_IDESC,
                               (k != 0 || ks != 0) ? 1u : 0u);
#pragma unroll
                for (int ks = 0; ks < 4; ks++)
                    mma_f16_ss(tmem, dAh + ks * 2, dBl + ks * 2, MMA_IDESC, 1u);
#pragma unroll
                for (int ks = 0; ks < 4; ks++)
                    mma_f16_ss(tmem, dAl + ks * 2, dBh + ks * 2, MMA_IDESC, 1u);
                TC_COMMIT(s ? mbar1 : mbar0);
            }
        }
        if (k + 2 < NCHUNK) {
            mbar_wait(s ? mbar1 : mbar0, (k >> 1) & 1);
            load_chunk(k + 2, stage);
        }
    }
    mbar_wait(mbar0, 1);
    mbar_wait(mbar1, 0);
    TC_FENCE_AFTER();
    __syncthreads();

    const bool doT = (YTh != nullptr);
    const int w = t >> 5;
    const int chal = w >> 2;
    const int lane = t & 31;
    const int rl = (w & 3) * 32 + lane;
    const int m = m0 + rl;
    const bool vm = (m < NCOLS);
    __nv_bfloat16* shh = (__nv_bfloat16*)dynsm;
    __nv_bfloat16* shl = shh + 128 * SST;

    for (int cb = 0; cb < 4; cb++) {
        const int c0 = chal * 128 + cb * 32;
        uint32_t regs[32];
        LDTM_X32(regs, tmem + c0);
        TC_WAIT_LD();
#pragma unroll
        for (int j = 0; j < 32; j++) {
            int n = n0 + c0 + j;
            float y = alpha * __uint_as_float(regs[j]);
            bool vn = (n < NNODES);
            if (beta != 0.f && vm && vn) y += beta * Xprev[(size_t)n * NCOLS + m];
            if (vm && vn) Yf[(size_t)n * NCOLS + m] = y;
            if (doT) {
                __nv_bfloat16 h, l;
                split_bf16(y, h, l);
                shh[rl * SST + c0 + j] = h;
                shl[rl * SST + c0 + j] = l;
            }
        }
    }
    if (doT) {
        __syncthreads();
        int r = t >> 1, half = t & 1;
        int m2 = m0 + r;
        if (m2 < NCOLS) {
#pragma unroll
            for (int v = 0; v < 16; v++) {
                int nn = n0 + half * 128 + v * 8;
                int sidx = r * SST + half * 128 + v * 8;
                if (nn + 8 <= NNODES) {
                    *(uint4*)(YTh + (size_t)m2 * KPAD + nn) = *(uint4*)&shh[sidx];
                    *(uint4*)(YTl + (size_t)m2 * KPAD + nn) = *(uint4*)&shl[sidx];
                } else {
                    for (int e = 0; e < 8; e++)
                        if (nn + e < NNODES) {
                            YTh[(size_t)m2 * KPAD + nn + e] = shh[sidx + e];
                            YTl[(size_t)m2 * KPAD + nn + e] = shl[sidx + e];
                        }
                }
            }
        }
    }
    __syncthreads();
    if (t == 0) { MBAR_INVAL(mbar0); MBAR_INVAL(mbar1); }
    __syncthreads();
    if ((t >> 5) == 0) {
        TC_RELINQ();
        TC_DEALLOC(tmem, 256);
    }
#else
    const int lane = t & 31;
    const int warp = t >> 5;
    const int wm = warp & 1;
    const int wn = warp >> 1;
    const int lg = lane >> 3, lr = lane & 7;

    float acc[4][8][4];
#pragma unroll
    for (int i = 0; i < 4; i++)
#pragma unroll
        for (int j = 0; j < 8; j++)
#pragma unroll
            for (int e = 0; e < 4; e++) acc[i][j][e] = 0.f;

    for (int chunk = 0; chunk < NCHUNK; chunk++) {
        load_chunk(chunk, 0);
        CP_WAIT0();
        __syncthreads();
#pragma unroll
        for (int ks = 0; ks < 4; ks++) {
            uint32_t ah[4][4], al[4][4];
#pragma unroll
            for (int am = 0; am < 4; am++) {
                int row = wm * 64 + am * 16 + (lg & 1) * 8 + lr;
                int koff = ks * 32 + (lg >> 1) * 16;
                uint32_t so = sw128((uint32_t)(row * 128 + koff));
                ldm4(ah[am], dyn_u32 + ST_AH + so);
                ldm4(al[am], dyn_u32 + ST_AL + so);
            }
            uint32_t bh[4][4], bl[4][4];
#pragma unroll
            for (int p = 0; p < 4; p++) {
                int row = wn * 64 + p * 16 + (lg >> 1) * 8 + lr;
                int koff = ks * 32 + (lg & 1) * 16;
                uint32_t so = sw128((uint32_t)(row * 128 + koff));
                ldm4(bh[p], dyn_u32 + ST_BH + so);
                ldm4(bl[p], dyn_u32 + ST_BL + so);
            }
#pragma unroll
            for (int am = 0; am < 4; am++)
#pragma unroll
                for (int an = 0; an < 8; an++) {
                    int p = an >> 1, h = (an & 1) * 2;
                    mma16816(acc[am][an], ah[am], bh[p][h], bh[p][h + 1]);
                    mma16816(acc[am][an], ah[am], bl[p][h], bl[p][h + 1]);
                    mma16816(acc[am][an], al[am], bh[p][h], bh[p][h + 1]);
                }
        }
        __syncthreads();
    }

    const bool doT = (YTh != nullptr);
#pragma unroll
    for (int am = 0; am < 4; am++) {
#pragma unroll
        for (int an = 0; an < 8; an++) {
            int mrow = m0 + wm * 64 + am * 16 + (lane >> 2);
            int ncol = n0 + wn * 64 + an * 8 + (lane & 3) * 2;
#pragma unroll
            for (int h = 0; h < 2; h++) {
                int m = mrow + h * 8;
                if (m >= NCOLS) continue;
#pragma unroll
                for (int e = 0; e < 2; e++) {
                    int n = ncol + e;
                    if (n >= NNODES) continue;
                    float y = alpha * acc[am][an][h * 2 + e];
                    if (beta != 0.f) y += beta * Xprev[(size_t)n * NCOLS + m];
                    Yf[(size_t)n * NCOLS + m] = y;
                    if (doT) {
                        __nv_bfloat16 hh, ll;
                        split_bf16(y, hh, ll);
                        YTh[(size_t)m * KPAD + n] = hh;
                        YTl[(size_t)m * KPAD + n] = ll;
                    }
                }
            }
        }
    }
#endif
}

// ---------------- tensor-core gate projection ----------------
// M=128 rows (8 nodes x 16 batch), N=128 outs, K=352 in 11x32 chunks
// smem: stage s (32KB): A_h 0, A_l 8192, W_h 16384, W_l 24576; rh staging at 65536 (32KB)
__global__ __launch_bounds__(256, 2)
void k_proj_gate_tc(const float* __restrict__ X0f, const float* __restrict__ X1a,
                    const float* __restrict__ X2a, const float* __restrict__ X1b,
                    const float* __restrict__ X2b,
                    const __nv_bfloat16* __restrict__ Wth, const __nv_bfloat16* __restrict__ Wtl,
                    const float* __restrict__ bg, const float* __restrict__ hx,
                    float* __restrict__ X0w,
                    __nv_bfloat16* __restrict__ X0Th, __nv_bfloat16* __restrict__ X0Tl,
                    float* __restrict__ ubuf) {
    extern __shared__ __align__(1024) unsigned char dynsm[];
    const int t = threadIdx.x;
    const int n0 = blockIdx.x * 8;
    const uint32_t dyn_u32 = smem_u32(dynsm);

#if HAS_TCGEN05
    __shared__ uint32_t s_tmem;
    __shared__ __align__(8) uint64_t s_mbar[2];
    uint32_t mb0 = smem_u32(&s_mbar[0]), mb1 = smem_u32(&s_mbar[1]);
    if ((t >> 5) == 0) TC_ALLOC(smem_u32(&s_tmem), 128);
    if (t == 0) { MBAR_INIT(mb0, 1); MBAR_INIT(mb1, 1); }
    __syncthreads();
    const uint32_t tmem = s_tmem;

    for (int k = 0; k < NCHUNK_P; k++) {
        const int s = k & 1;
        const uint32_t stage = dyn_u32 + s * 32768;
        if (k >= 2) mbar_wait(s ? mb1 : mb0, ((k >> 1) + 1) & 1);
#pragma unroll
        for (int i = 0; i < 2; i++) {
            int idx = t + i * 256;
            int row = idx >> 2, seg = idx & 3;
            uint32_t so = sw64((uint32_t)(row * 64 + seg * 16));
            CP_ASYNC16(stage + 16384 + so, Wth + (size_t)row * KP + k * 32 + seg * 8);
            CP_ASYNC16(stage + 24576 + so, Wtl + (size_t)row * KP + k * 32 + seg * 8);
        }
        CP_COMMIT();
        {
            int b = t & 15;
#pragma unroll
            for (int it = 0; it < 16; it++) {
                int p = it * 16 + (t >> 4);
                int nl = p >> 5, jl = p & 31;
                int j = k * 32 + jl;
                float v = 0.f;
                if (j < 330) {
                    int m = j / 66, c = j - m * 66;
                    const float* src = (m == 0) ? X0f : (m == 1) ? X1a : (m == 2) ? X2a
                                       : (m == 3) ? X1b : X2b;
                    v = src[(size_t)(n0 + nl) * NCOLS + c * 16 + b];
                }
                __nv_bfloat16 h, l;
                split_bf16(v, h, l);
                uint32_t so = sw64((uint32_t)((nl * 16 + b) * 64 + jl * 2));
                *(__nv_bfloat16*)(dynsm + s * 32768 + so) = h;
                *(__nv_bfloat16*)(dynsm + s * 32768 + 8192 + so) = l;
            }
        }
        CP_WAIT0();
        __syncthreads();
        if ((t >> 5) == 0) {
            FENCE_ASYNC();
            if (elect_one()) {
                uint64_t dAh = make_desc64(stage), dAl = make_desc64(stage + 8192);
                uint64_t dWh = make_desc64(stage + 16384), dWl = make_desc64(stage + 24576);
#pragma unroll
                for (int ks = 0; ks < 2; ks++) {
                    mma_f16_ss(tmem, dAh + ks * 2, dWh + ks * 2, IDESC_N128,
                               (k != 0 || ks != 0) ? 1u : 0u);
                    mma_f16_ss(tmem, dAh + ks * 2, dWl + ks * 2, IDESC_N128, 1u);
                    mma_f16_ss(tmem, dAl + ks * 2, dWh + ks * 2, IDESC_N128, 1u);
                }
                TC_COMMIT(s ? mb1 : mb0);
            }
        }
    }
    mbar_wait(mb0, 1);  // chunks 0,2,4,6,8,10 -> 6 completions
    mbar_wait(mb1, 0);  // 5 completions
    TC_FENCE_AFTER();
    __syncthreads();

    float* stage_rh = (float*)(dynsm + 65536);  // 128 x 64
    const int w = t >> 5, l = t & 31;
    if (w < 4) {
        int row = w * 32 + l;
        int nl = row >> 4, b = row & 15;
        int n = n0 + nl;
        for (int cb = 0; cb < 4; cb++) {
            uint32_t regs[32];
            LDTM_X32(regs, tmem + cb * 32);
            TC_WAIT_LD();
#pragma unroll
            for (int jj = 0; jj < 32; jj++) {
                int o = cb * 32 + jj;
                float acc = __uint_as_float(regs[jj]) + bg[o];
                float sig = 1.f / (1.f + __expf(-acc));
                if (o < NUNITS) {
                    float h = hx[(size_t)b * HXSZ + n * NUNITS + o];
                    stage_rh[row * 64 + o] = sig * h;
                } else {
                    ubuf[(size_t)b * HXSZ + n * NUNITS + (o - NUNITS)] = sig;
                }
            }
        }
    }
    __syncthreads();
    // X0 fp32: cols [32,1056), coalesced
#pragma unroll
    for (int i = 0; i < 32; i++) {
        int idx = t + i * 256;
        int nl = idx >> 10, q = idx & 1023;
        int o = q >> 4, b = q & 15;
        X0w[(size_t)(n0 + nl) * NCOLS + 32 + q] = stage_rh[(nl * 16 + b) * 64 + o];
    }
    // X0T hi/lo: row rr=32+q, 8-node 16B vectors
#pragma unroll
    for (int i = 0; i < 4; i++) {
        int q = t + i * 256;
        int o = q >> 4, b = q & 15;
        int rr = 32 + q;
        __nv_bfloat16 hv[8], lv[8];
#pragma unroll
        for (int nl = 0; nl < 8; nl++)
            split_bf16(stage_rh[(nl * 16 + b) * 64 + o], hv[nl], lv[nl]);
        *(uint4*)(X0Th + (size_t)rr * KPAD + n0) = *(uint4*)hv;
        *(uint4*)(X0Tl + (size_t)rr * KPAD + n0) = *(uint4*)lv;
    }
    __syncthreads();
    if (t == 0) { MBAR_INVAL(mb0); MBAR_INVAL(mb1); }
    __syncthreads();
    if ((t >> 5) == 0) {
        TC_RELINQ();
        TC_DEALLOC(tmem, 128);
    }
#else
    int o = t;
    if (o < NGATE) {
        for (int nl = 0; nl < 8; nl++) {
            int n = n0 + nl;
            for (int b = 0; b < 16; b++) {
                float acc = bg[o];
                for (int j = 0; j < 330; j++) {
                    int m = j / 66, c = j - m * 66;
                    const float* src = (m == 0) ? X0f : (m == 1) ? X1a : (m == 2) ? X2a
                                       : (m == 3) ? X1b : X2b;
                    float wv = __bfloat162float(Wth[(size_t)o * KP + j]) +
                               __bfloat162float(Wtl[(size_t)o * KP + j]);
                    acc += src[(size_t)n * NCOLS + c * 16 + b] * wv;
                }
                float sig = 1.f / (1.f + __expf(-acc));
                if (o < NUNITS) {
                    float h = hx[(size_t)b * HXSZ + n * NUNITS + o];
                    float rh = sig * h;
                    X0w[(size_t)n * NCOLS + (2 + o) * 16 + b] = rh;
                    __nv_bfloat16 hi, lo;
                    split_bf16(rh, hi, lo);
                    X0Th[(size_t)((2 + o) * 16 + b) * KPAD + n] = hi;
                    X0Tl[(size_t)((2 + o) * 16 + b) * KPAD + n] = lo;
                } else {
                    ubuf[(size_t)b * HXSZ + n * NUNITS + (o - NUNITS)] = sig;
                }
            }
        }
    }
#endif
}

// ---------------- tensor-core candidate projection + GRU combine ----------------
// N=64; smem stage (24KB): A_h 0, A_l 8192, W_h 16384, W_l 20480
__global__ __launch_bounds__(256, 2)
void k_proj_cand_tc(const float* __restrict__ X0f, const float* __restrict__ X1a,
                    const float* __restrict__ X2a, const float* __restrict__ X1b,
                    const float* __restrict__ X2b,
                    const __nv_bfloat16* __restrict__ Wth, const __nv_bfloat16* __restrict__ Wtl,
                    const float* __restrict__ bc, const float* __restrict__ hx,
                    const float* __restrict__ ubuf, float* __restrict__ out) {
    extern __shared__ __align__(1024) unsigned char dynsm[];
    const int t = threadIdx.x;
    const int n0 = blockIdx.x * 8;
    const uint32_t dyn_u32 = smem_u32(dynsm);

#if HAS_TCGEN05
    __shared__ uint32_t s_tmem;
    __shared__ __align__(8) uint64_t s_mbar[2];
    uint32_t mb0 = smem_u32(&s_mbar[0]), mb1 = smem_u32(&s_mbar[1]);
    if ((t >> 5) == 0) TC_ALLOC(smem_u32(&s_tmem), 64);
    if (t == 0) { MBAR_INIT(mb0, 1); MBAR_INIT(mb1, 1); }
    __syncthreads();
    const uint32_t tmem = s_tmem;

    for (int k = 0; k < NCHUNK_P; k++) {
        const int s = k & 1;
        const uint32_t stage = dyn_u32 + s * 24576;
        if (k >= 2) mbar_wait(s ? mb1 : mb0, ((k >> 1) + 1) & 1);
        {
            int idx = t;  // 64 rows x 4 segs = 256
            int row = idx >> 2, seg = idx & 3;
            uint32_t so = sw64((uint32_t)(row * 64 + seg * 16));
            CP_ASYNC16(stage + 16384 + so, Wth + (size_t)row * KP + k * 32 + seg * 8);
            CP_ASYNC16(stage + 20480 + so, Wtl + (size_t)row * KP + k * 32 + seg * 8);
        }
        CP_COMMIT();
        {
            int b = t & 15;
#pragma unroll
            for (int it = 0; it < 16; it++) {
                int p = it * 16 + (t >> 4);
                int nl = p >> 5, jl = p & 31;
                int j = k * 32 + jl;
                float v = 0.f;
                if (j < 330) {
                    int m = j / 66, c = j - m * 66;
                    const float* src = (m == 0) ? X0f : (m == 1) ? X1a : (m == 2) ? X2a
                                       : (m == 3) ? X1b : X2b;
                    v = src[(size_t)(n0 + nl) * NCOLS + c * 16 + b];
                }
                __nv_bfloat16 h, l;
                split_bf16(v, h, l);
                uint32_t so = sw64((uint32_t)((nl * 16 + b) * 64 + jl * 2));
                *(__nv_bfloat16*)(dynsm + s * 24576 + so) = h;
                *(__nv_bfloat16*)(dynsm + s * 24576 + 8192 + so) = l;
            }
        }
        CP_WAIT0();
        __syncthreads();
        if ((t >> 5) == 0) {
            FENCE_ASYNC();
            if (elect_one()) {
                uint64_t dAh = make_desc64(stage), dAl = make_desc64(stage + 8192);
                uint64_t dWh = make_desc64(stage + 16384), dWl = make_desc64(stage + 20480);
#pragma unroll
                for (int ks = 0; ks < 2; ks++) {
                    mma_f16_ss(tmem, dAh + ks * 2, dWh + ks * 2, IDESC_N64,
                               (k != 0 || ks != 0) ? 1u : 0u);
                    mma_f16_ss(tmem, dAh + ks * 2, dWl + ks * 2, IDESC_N64, 1u);
                    mma_f16_ss(tmem, dAl + ks * 2, dWh + ks * 2, IDESC_N64, 1u);
                }
                TC_COMMIT(s ? mb1 : mb0);
            }
        }
    }
    mbar_wait(mb0, 1);
    mbar_wait(mb1, 0);
    TC_FENCE_AFTER();
    __syncthreads();

    const int w = t >> 5, l = t & 31;
    if (w < 4) {
        int row = w * 32 + l;
        int nl = row >> 4, b = row & 15;
        int n = n0 + nl;
        for (int cb = 0; cb < 2; cb++) {
            uint32_t regs[32];
            LDTM_X32(regs, tmem + cb * 32);
            TC_WAIT_LD();
#pragma unroll
            for (int jj = 0; jj < 32; jj++) {
                int o = cb * 32 + jj;
                float acc = __uint_as_float(regs[jj]) + bc[o];
                float cc = tanhf(acc);
                size_t ix = (size_t)b * HXSZ + n * NUNITS + o;
                float u = ubuf[ix];
                float h = hx[ix];
                out[ix] = u * h + (1.f - u) * cc;
            }
        }
    }
    __syncthreads();
    if (t == 0) { MBAR_INVAL(mb0); MBAR_INVAL(mb1); }
    __syncthreads();
    if ((t >> 5) == 0) {
        TC_RELINQ();
        TC_DEALLOC(tmem, 64);
    }
#else
    int o = t;
    if (o < NUNITS) {
        for (int nl = 0; nl < 8; nl++) {
            int n = n0 + nl;
            for (int b = 0; b < 16; b++) {
                float acc = bc[o];
                for (int j = 0; j < 330; j++) {
                    int m = j / 66, c = j - m * 66;
                    const float* src = (m == 0) ? X0f : (m == 1) ? X1a : (m == 2) ? X2a
                                       : (m == 3) ? X1b : X2b;
                    float wv = __bfloat162float(Wth[(size_t)o * KP + j]) +
                               __bfloat162float(Wtl[(size_t)o * KP + j]);
                    acc += src[(size_t)n * NCOLS + c * 16 + b] * wv;
                }
                float cc = tanhf(acc);
                size_t ix = (size_t)b * HXSZ + n * NUNITS + o;
                float u = ubuf[ix];
                float h = hx[ix];
                out[ix] = u * h + (1.f - u) * cc;
            }
        }
    }
#endif
}

// ---------------- launch ----------------
extern "C" void kernel_launch(void* const* d_in, const int* in_sizes, int n_in,
                              void* d_out, int out_size) {
    const float* inputs = (const float*)d_in[0];
    const float* hx     = (const float*)d_in[1];
    const float* adj    = (const float*)d_in[2];
    const float* Wg     = (const float*)d_in[3];
    const float* bg     = (const float*)d_in[4];
    const float* Wc     = (const float*)d_in[5];
    const float* bc     = (const float*)d_in[6];
    float* out = (float*)d_out;

    __nv_bfloat16 *S0h, *S0l, *S1h, *S1l, *X0Th, *X0Tl, *X1aTh, *X1aTl, *X1bTh, *X1bTl;
    __nv_bfloat16 *Wgth, *Wgtl, *Wcth, *Wctl;
    float *X0, *X1a, *X2a, *X1b, *X2b, *invdr, *dcol, *invdc, *ubuf;
    cudaGetSymbolAddress((void**)&S0h, g_S0h);
    cudaGetSymbolAddress((void**)&S0l, g_S0l);
    cudaGetSymbolAddress((void**)&S1h, g_S1h);
    cudaGetSymbolAddress((void**)&S1l, g_S1l);
    cudaGetSymbolAddress((void**)&X0Th, g_X0Th);
    cudaGetSymbolAddress((void**)&X0Tl, g_X0Tl);
    cudaGetSymbolAddress((void**)&X1aTh, g_X1aTh);
    cudaGetSymbolAddress((void**)&X1aTl, g_X1aTl);
    cudaGetSymbolAddress((void**)&X1bTh, g_X1bTh);
    cudaGetSymbolAddress((void**)&X1bTl, g_X1bTl);
    cudaGetSymbolAddress((void**)&X0, g_X0);
    cudaGetSymbolAddress((void**)&X1a, g_X1a);
    cudaGetSymbolAddress((void**)&X2a, g_X2a);
    cudaGetSymbolAddress((void**)&X1b, g_X1b);
    cudaGetSymbolAddress((void**)&X2b, g_X2b);
    cudaGetSymbolAddress((void**)&Wgth, g_Wgth);
    cudaGetSymbolAddress((void**)&Wgtl, g_Wgtl);
    cudaGetSymbolAddress((void**)&Wcth, g_Wcth);
    cudaGetSymbolAddress((void**)&Wctl, g_Wctl);
    cudaGetSymbolAddress((void**)&invdr, g_invdr);
    cudaGetSymbolAddress((void**)&dcol, g_dcol);
    cudaGetSymbolAddress((void**)&invdc, g_invdc);
    cudaGetSymbolAddress((void**)&ubuf, g_u);

    cudaFuncSetAttribute(k_gemm_tc, cudaFuncAttributeMaxDynamicSharedMemorySize, SMEM_DYN);
    cudaFuncSetAttribute(k_proj_gate_tc, cudaFuncAttributeMaxDynamicSharedMemorySize, 98304);
    cudaFuncSetAttribute(k_proj_cand_tc, cudaFuncAttributeMaxDynamicSharedMemorySize, 49152);

    // 1-5: degrees + supports + X0T
    k_rowsum<<<NNODES, 256>>>(adj, invdr, dcol);
    {
        dim3 g((NNODES + 255) / 256, 24);
        k_colsum_part<<<g, 256>>>(adj, dcol);
    }
    {
        dim3 g(NPADS / 32, KPAD / 32);
        k_buildS0_split<<<g, dim3(32, 8)>>>(adj, invdr, S0h, S0l, dcol, invdc);
    }
    {
        dim3 g((KPAD + 255) / 256, NPADS);
        k_buildS1_split<<<g, 256>>>(adj, invdc, S1h, S1l);
    }
    k_buildX0T<<<1024, 256>>>(inputs, hx, X0Th, X0Tl);

    dim3 ggrid(NPADS / NT, MPAD / MT, 2);  // 12 x 9 x 2

    // 6: GEMM1 (X1 = S @ x0)
    k_gemm_tc<<<ggrid, 256, SMEM_DYN>>>(X0Th, X0Tl, X0Th, X0Tl,
                                        S0h, S0l, S1h, S1l,
                                        nullptr, X1a, X1b,
                                        X1aTh, X1aTl, X1bTh, X1bTl, 1.f, 0.f);
    // 7-8: X0 fp32 + pads
    k_buildX0<<<592, 256>>>(inputs, hx, X0);
    k_zero_padsT<<<(PADELEMS + 255) / 256, 256>>>(X1aTh, X1aTl, X1bTh, X1bTl);
    // 9: GEMM2 (X2 = 2 S X1 - X0)
    k_gemm_tc<<<ggrid, 256, SMEM_DYN>>>(X1aTh, X1aTl, X1bTh, X1bTl,
                                        S0h, S0l, S1h, S1l,
                                        X0, X2a, X2b,
                                        nullptr, nullptr, nullptr, nullptr, 2.f, -1.f);
    // 10-11: weight transposes
    k_buildWt<<<176, 256>>>(Wg, NGATE, Wgth, Wgtl);
    k_buildWt<<<88, 256>>>(Wc, NUNITS, Wcth, Wctl);
    // 12: gate projection (writes r*hx into X0 + X0T, u into ubuf)
    k_proj_gate_tc<<<NBLK_P, 256, 98304>>>(X0, X1a, X2a, X1b, X2b,
                                           Wgth, Wgtl, bg, hx,
                                           X0, X0Th, X0Tl, ubuf);
    // 13-14: candidate gconv GEMMs
    k_gemm_tc<<<ggrid, 256, SMEM_DYN>>>(X0Th, X0Tl, X0Th, X0Tl,
                                        S0h, S0l, S1h, S1l,
                                        nullptr, X1a, X1b,
                                        X1aTh, X1aTl, X1bTh, X1bTl, 1.f, 0.f);
    k_gemm_tc<<<ggrid, 256, SMEM_DYN>>>(X1aTh, X1aTl, X1bTh, X1bTl,
                                        S0h, S0l, S1h, S1l,
                                        X0, X2a, X2b,
                                        nullptr, nullptr, nullptr, nullptr, 2.f, -1.f);
    // 15: candidate projection + GRU combine
    k_proj_cand_tc<<<NBLK_P, 256, 49152>>>(X0, X1a, X2a, X1b, X2b,
                                           Wcth, Wctl, bc, hx, ubuf, out);
}

// round 8
// speedup vs baseline: 1.2305x; 1.2305x over previous
#include <cuda_runtime.h>
#include <cuda_bf16.h>
#include <cstdint>
#include <cstddef>

#define NNODES 3000
#define NFEAT 2
#define NUNITS 64
#define BATCH 16
#define CCH (NFEAT + NUNITS)       // 66
#define NCOLS (CCH * BATCH)        // 1056
#define NGATE (2 * NUNITS)         // 128
#define HXSZ (NNODES * NUNITS)

#define KPAD 3008                  // 47 * 64
#define MPAD 1152
#define NPADS 3072
#define NCHUNK 47
#define MT 128
#define NT 256

#if defined(__CUDA_ARCH_FEAT_SM103_ALL) || defined(__CUDA_ARCH_FEAT_SM100_ALL) || \
    (defined(__CUDA_ARCH_SPECIFIC__) && (__CUDA_ARCH_SPECIFIC__ >= 1000))
#define HAS_TCGEN05 1
#else
#define HAS_TCGEN05 0
#endif

#define MMA_IDESC ((1u<<4)|(1u<<7)|(1u<<10)|((NT/8)<<17)|((MT/16)<<24))

__device__ __nv_bfloat16 g_S0h[(size_t)NPADS * KPAD];
__device__ __nv_bfloat16 g_S0l[(size_t)NPADS * KPAD];
__device__ __nv_bfloat16 g_S1h[(size_t)NPADS * KPAD];
__device__ __nv_bfloat16 g_S1l[(size_t)NPADS * KPAD];
__device__ __nv_bfloat16 g_X0Th[(size_t)MPAD * KPAD];
__device__ __nv_bfloat16 g_X0Tl[(size_t)MPAD * KPAD];
__device__ __nv_bfloat16 g_X1aTh[(size_t)MPAD * KPAD];
__device__ __nv_bfloat16 g_X1aTl[(size_t)MPAD * KPAD];
__device__ __nv_bfloat16 g_X1bTh[(size_t)MPAD * KPAD];
__device__ __nv_bfloat16 g_X1bTl[(size_t)MPAD * KPAD];
__device__ float g_X0[(size_t)NNODES * NCOLS];
__device__ float g_X1a[(size_t)NNODES * NCOLS];
__device__ float g_X2a[(size_t)NNODES * NCOLS];
__device__ float g_X1b[(size_t)NNODES * NCOLS];
__device__ float g_X2b[(size_t)NNODES * NCOLS];
__device__ float g_invdr[NNODES];
__device__ float g_dcol[NNODES];
__device__ float g_invdc[NNODES];
__device__ float g_u[(size_t)BATCH * NNODES * NUNITS];

__device__ __forceinline__ uint32_t smem_u32(const void* p) {
    uint32_t a;
    asm("{ .reg .u64 t; cvta.to.shared.u64 t, %1; cvt.u32.u64 %0, t; }" : "=r"(a) : "l"(p));
    return a;
}
static __device__ __forceinline__ uint32_t sw128(uint32_t off) { return off ^ ((off >> 3) & 0x70); }
static __device__ __forceinline__ void split_bf16(float v, __nv_bfloat16& h, __nv_bfloat16& l) {
    h = __float2bfloat16(v);
    l = __float2bfloat16(v - __bfloat162float(h));
}

#define CP_ASYNC16(dst, src) \
    asm volatile("cp.async.cg.shared.global [%0], [%1], 16;" :: "r"(dst), "l"(src) : "memory")
#define CP_COMMIT() asm volatile("cp.async.commit_group;" ::: "memory")
#define CP_WAIT1()  asm volatile("cp.async.wait_group 1;" ::: "memory")
#define CP_WAIT0()  asm volatile("cp.async.wait_group 0;" ::: "memory")

#if HAS_TCGEN05
__device__ __forceinline__ uint32_t elect_one() {
    uint32_t pred;
    asm volatile("{\n\t.reg .pred p;\n\telect.sync _|p, 0xFFFFFFFF;\n\tselp.b32 %0, 1, 0, p;\n\t}"
                 : "=r"(pred));
    return pred;
}
#define MBAR_INIT(a, c) asm volatile("mbarrier.init.shared.b64 [%0], %1;" :: "r"(a), "r"(c) : "memory")
#define MBAR_INVAL(a)   asm volatile("mbarrier.inval.shared.b64 [%0];" :: "r"(a) : "memory")
__device__ __forceinline__ void mbar_wait(uint32_t addr, uint32_t parity) {
    uint32_t done;
    asm volatile("{\n\t.reg .pred p;\n\t"
                 "mbarrier.try_wait.parity.acquire.cta.shared::cta.b64 p, [%1], %2;\n\t"
                 "selp.b32 %0, 1, 0, p;\n\t}"
                 : "=r"(done) : "r"(addr), "r"(parity) : "memory");
    if (!done) {
        asm volatile("{\n\t.reg .pred P1;\n\t"
                     "WL_%=:\n\t"
                     "mbarrier.try_wait.parity.acquire.cta.shared::cta.b64 P1, [%0], %1, 0x989680;\n\t"
                     "@P1 bra.uni WD_%=;\n\t"
                     "bra.uni WL_%=;\n\t"
                     "WD_%=:\n\t}"
                     :: "r"(addr), "r"(parity) : "memory");
    }
}
#define TC_ALLOC(sm, n)   asm volatile("tcgen05.alloc.cta_group::1.sync.aligned.shared::cta.b32 [%0], %1;" :: "r"(sm), "r"(n) : "memory")
#define TC_DEALLOC(t, n)  asm volatile("tcgen05.dealloc.cta_group::1.sync.aligned.b32 %0, %1;" :: "r"(t), "r"(n))
#define TC_RELINQ()       asm volatile("tcgen05.relinquish_alloc_permit.cta_group::1.sync.aligned;")
#define TC_COMMIT(mb)     asm volatile("tcgen05.commit.cta_group::1.mbarrier::arrive::one.shared::cluster.b64 [%0];" :: "r"(mb) : "memory")
#define TC_FENCE_AFTER()  asm volatile("tcgen05.fence::after_thread_sync;" ::: "memory")
#define TC_WAIT_LD()      asm volatile("tcgen05.wait::ld.sync.aligned;" ::: "memory")
#define FENCE_ASYNC()     asm volatile("fence.proxy.async.shared::cta;" ::: "memory")

__device__ __forceinline__ void mma_f16_ss(uint32_t d, uint64_t a, uint64_t b,
                                           uint32_t idesc, uint32_t en) {
    asm volatile("{\n\t.reg .pred p;\n\tsetp.ne.u32 p, %4, 0;\n\t"
                 "tcgen05.mma.cta_group::1.kind::f16 [%0], %1, %2, %3, {%5,%5,%5,%5}, p;\n\t}"
                 :: "r"(d), "l"(a), "l"(b), "r"(idesc), "r"(en), "r"(0u) : "memory");
}

#define LDTM_X32(r, addr) \
    asm volatile("tcgen05.ld.sync.aligned.32x32b.x32.b32 " \
        "{%0,%1,%2,%3,%4,%5,%6,%7,%8,%9,%10,%11,%12,%13,%14,%15," \
        "%16,%17,%18,%19,%20,%21,%22,%23,%24,%25,%26,%27,%28,%29,%30,%31}, [%32];" \
        : "=r"((r)[0]),"=r"((r)[1]),"=r"((r)[2]),"=r"((r)[3]),"=r"((r)[4]),"=r"((r)[5]), \
          "=r"((r)[6]),"=r"((r)[7]),"=r"((r)[8]),"=r"((r)[9]),"=r"((r)[10]),"=r"((r)[11]), \
          "=r"((r)[12]),"=r"((r)[13]),"=r"((r)[14]),"=r"((r)[15]),"=r"((r)[16]),"=r"((r)[17]), \
          "=r"((r)[18]),"=r"((r)[19]),"=r"((r)[20]),"=r"((r)[21]),"=r"((r)[22]),"=r"((r)[23]), \
          "=r"((r)[24]),"=r"((r)[25]),"=r"((r)[26]),"=r"((r)[27]),"=r"((r)[28]),"=r"((r)[29]), \
          "=r"((r)[30]),"=r"((r)[31]) : "r"(addr))

static __device__ __forceinline__ uint64_t make_desc(uint32_t addr) {
    const uint64_t base = (uint64_t(2) << 61) | (uint64_t(1) << 46) |
                          (uint64_t(64) << 32) | (uint64_t(1) << 16);
    return base | ((uint64_t)(addr >> 4) & 0x3FFF);
}
#else
__device__ __forceinline__ void ldm4(uint32_t* r, uint32_t addr) {
    asm volatile("ldmatrix.sync.aligned.m8n8.x4.shared.b16 {%0,%1,%2,%3}, [%4];"
                 : "=r"(r[0]), "=r"(r[1]), "=r"(r[2]), "=r"(r[3]) : "r"(addr));
}
__device__ __forceinline__ void mma16816(float* c, const uint32_t* a, uint32_t b0, uint32_t b1) {
    asm volatile("mma.sync.aligned.m16n8k16.row.col.f32.bf16.bf16.f32 "
                 "{%0,%1,%2,%3}, {%4,%5,%6,%7}, {%8,%9}, {%0,%1,%2,%3};"
                 : "+f"(c[0]), "+f"(c[1]), "+f"(c[2]), "+f"(c[3])
                 : "r"(a[0]), "r"(a[1]), "r"(a[2]), "r"(a[3]), "r"(b0), "r"(b1));
}
#endif

// ---------------- degree kernels (R4) ----------------
__global__ void k_rowsum(const float* __restrict__ A, float* __restrict__ invdr) {
    __shared__ float red[256];
    int r = blockIdx.x;
    float s = 0.f;
    for (int j = threadIdx.x; j < NNODES; j += 256) s += A[(size_t)r * NNODES + j];
    red[threadIdx.x] = s;
    __syncthreads();
    for (int w = 128; w > 0; w >>= 1) {
        if (threadIdx.x < w) red[threadIdx.x] += red[threadIdx.x + w];
        __syncthreads();
    }
    if (threadIdx.x == 0) {
        float d = red[0];
        invdr[r] = (d > 0.f) ? 1.f / d : 0.f;
    }
}
__global__ void k_zero_dcol(float* __restrict__ dcol) {
    int j = blockIdx.x * blockDim.x + threadIdx.x;
    if (j < NNODES) dcol[j] = 0.f;
}
__global__ void k_colsum_part(const float* __restrict__ A, float* __restrict__ dcol) {
    int j = blockIdx.x * blockDim.x + threadIdx.x;
    if (j >= NNODES) return;
    int r0 = blockIdx.y * 125;
    float s = 0.f;
    for (int r = r0; r < r0 + 125; r++) s += A[(size_t)r * NNODES + j];
    atomicAdd(&dcol[j], s);
}
__global__ void k_invert_dcol(const float* __restrict__ dcol, float* __restrict__ invdc) {
    int j = blockIdx.x * blockDim.x + threadIdx.x;
    if (j < NNODES) {
        float d = dcol[j];
        invdc[j] = (d > 0.f) ? 1.f / d : 0.f;
    }
}

// ---------------- supports ----------------
__global__ void k_buildS0_split(const float* __restrict__ A, const float* __restrict__ invdr,
                                __nv_bfloat16* __restrict__ Sh, __nv_bfloat16* __restrict__ Sl) {
    __shared__ float sm[32][33];
    int i0 = blockIdx.x * 32;
    int j0 = blockIdx.y * 32;
    int tx = threadIdx.x, ty = threadIdx.y;
#pragma unroll
    for (int r = 0; r < 4; r++) {
        int j = j0 + ty + r * 8;
        int i = i0 + tx;
        sm[ty + r * 8][tx] = (j < NNODES && i < NNODES) ? A[(size_t)j * NNODES + i] : 0.f;
    }
    __syncthreads();
#pragma unroll
    for (int r = 0; r < 4; r++) {
        int i = i0 + ty + r * 8;
        int j = j0 + tx;
        if (i < NPADS && j < KPAD) {
            float v = (i < NNODES && j < NNODES) ? sm[tx][ty + r * 8] * invdr[j] : 0.f;
            __nv_bfloat16 h, l;
            split_bf16(v, h, l);
            Sh[(size_t)i * KPAD + j] = h;
            Sl[(size_t)i * KPAD + j] = l;
        }
    }
}
// vectorized: 8 cols per thread
__global__ void k_buildS1_splitv(const float* __restrict__ A, const float* __restrict__ invdc,
                                 __nv_bfloat16* __restrict__ Sh, __nv_bfloat16* __restrict__ Sl) {
    int gid = blockIdx.x * blockDim.x + threadIdx.x;
    int i = gid / 376;
    int jj = gid - i * 376;
    if (i >= NPADS) return;
    int j0 = jj * 8;
    __nv_bfloat16 hv[8], lv[8];
    if (i < NNODES && j0 + 8 <= NNODES) {
        const float* ap = A + (size_t)i * NNODES + j0;
        float4 a0 = *(const float4*)ap;
        float4 a1 = *(const float4*)(ap + 4);
        float va[8] = {a0.x, a0.y, a0.z, a0.w, a1.x, a1.y, a1.z, a1.w};
#pragma unroll
        for (int e = 0; e < 8; e++) {
            float v = va[e] * invdc[j0 + e];
            split_bf16(v, hv[e], lv[e]);
        }
    } else {
#pragma unroll
        for (int e = 0; e < 8; e++) {
            int j = j0 + e;
            float v = (i < NNODES && j < NNODES) ? A[(size_t)i * NNODES + j] * invdc[j] : 0.f;
            split_bf16(v, hv[e], lv[e]);
        }
    }
    *(uint4*)(Sh + (size_t)i * KPAD + j0) = *(const uint4*)hv;
    *(uint4*)(Sl + (size_t)i * KPAD + j0) = *(const uint4*)lv;
}

// ---------------- combined X0 builder: X0 fp32 + X0T hi/lo, coalesced via smem ----------------
// one block = 16 node slots (grid 188 covers n0 0..3007 incl. col pads)
__global__ void k_buildX0_all(const float* __restrict__ inputs, const float* __restrict__ hx,
                              float* __restrict__ X0,
                              __nv_bfloat16* __restrict__ Th, __nv_bfloat16* __restrict__ Tl) {
    extern __shared__ float sbuf[];
    float* s_hx = sbuf;             // [b*1025 + nl*64 + o], 16*1025 floats
    float* s_inp = sbuf + 16400;    // [b*32 + nl*2 + c], 512 floats
    const int t = threadIdx.x;
    const int n0 = blockIdx.x * 16;

    for (int b = 0; b < 16; b++) {
        const float* base = hx + (size_t)b * HXSZ + (size_t)n0 * NUNITS;
        for (int idx = t; idx < 1024; idx += 256) {
            int nl = idx >> 6;
            float v = (n0 + nl < NNODES) ? base[idx] : 0.f;
            s_hx[b * 1025 + idx] = v;
        }
    }
    for (int idx = t; idx < 512; idx += 256) {
        int b = idx >> 5, q = idx & 31, nl = q >> 1, c = q & 1;
        float v = (n0 + nl < NNODES)
                      ? inputs[(size_t)b * (NNODES * NFEAT) + (size_t)(n0 + nl) * NFEAT + c]
                      : 0.f;
        s_inp[b * 32 + nl * 2 + c] = v;
    }
    __syncthreads();

    // X0 fp32 rows
    for (int idx = t; idx < 16 * NCOLS; idx += 256) {
        int nl = idx / NCOLS;
        int r = idx - nl * NCOLS;
        int n = n0 + nl;
        if (n >= NNODES) continue;
        int c = r >> 4, b = r & 15;
        float v = (c < NFEAT) ? s_inp[b * 32 + nl * 2 + c]
                              : s_hx[b * 1025 + nl * 64 + (c - NFEAT)];
        X0[(size_t)n * NCOLS + r] = v;
    }
    // X0T hi/lo (16B vectors of 8 nodes)
    for (int idx = t; idx < NCOLS * 2; idx += 256) {
        int r = idx >> 1, half = idx & 1;
        int c = r >> 4, b = r & 15;
        __nv_bfloat16 hv[8], lv[8];
#pragma unroll
        for (int q = 0; q < 8; q++) {
            int nl = half * 8 + q;
            float v = 0.f;
            if (n0 + nl < NNODES)
                v = (c < NFEAT) ? s_inp[b * 32 + nl * 2 + c]
                                : s_hx[b * 1025 + nl * 64 + (c - NFEAT)];
            split_bf16(v, hv[q], lv[q]);
        }
        *(uint4*)(Th + (size_t)r * KPAD + n0 + half * 8) = *(const uint4*)hv;
        *(uint4*)(Tl + (size_t)r * KPAD + n0 + half * 8) = *(const uint4*)lv;
    }
}

// ---------------- pad zeroing for 6 transposed operands ----------------
#define PADELEMS ((MPAD - NCOLS) * KPAD + NCOLS * 8)
__global__ void k_zero_padsT6(__nv_bfloat16* a, __nv_bfloat16* b, __nv_bfloat16* c,
                              __nv_bfloat16* d, __nv_bfloat16* e, __nv_bfloat16* f) {
    int idx = blockIdx.x * blockDim.x + threadIdx.x;
    if (idx >= PADELEMS) return;
    size_t off;
    if (idx < (MPAD - NCOLS) * KPAD) {
        int r = NCOLS + idx / KPAD;
        int col = idx % KPAD;
        off = (size_t)r * KPAD + col;
    } else {
        int k = idx - (MPAD - NCOLS) * KPAD;
        int r = k >> 3;
        int col = NNODES + (k & 7);
        off = (size_t)r * KPAD + col;
    }
    __nv_bfloat16 z = __float2bfloat16(0.f);
    a[off] = z; b[off] = z; c[off] = z; d[off] = z; e[off] = z; f[off] = z;
}

// ---------------- main tensor-core GEMM (R4 config, verbatim) ----------------
#define ST_AH 0
#define ST_AL 16384
#define ST_BH 32768
#define ST_BL 65536
#define STAGE_SZ 98304
#define SMEM_DYN (2 * STAGE_SZ)
#define SST 264

__global__ __launch_bounds__(256, 1)
void k_gemm_tc(const __nv_bfloat16* __restrict__ Ah0, const __nv_bfloat16* __restrict__ Al0,
               const __nv_bfloat16* __restrict__ Ah1, const __nv_bfloat16* __restrict__ Al1,
               const __nv_bfloat16* __restrict__ Bh0, const __nv_bfloat16* __restrict__ Bl0,
               const __nv_bfloat16* __restrict__ Bh1, const __nv_bfloat16* __restrict__ Bl1,
               const float* __restrict__ Xprev,
               float* __restrict__ Yf0, float* __restrict__ Yf1,
               __nv_bfloat16* __restrict__ YTh0, __nv_bfloat16* __restrict__ YTl0,
               __nv_bfloat16* __restrict__ YTh1, __nv_bfloat16* __restrict__ YTl1,
               float alpha, float beta) {
    extern __shared__ __align__(1024) unsigned char dynsm[];
    const int t = threadIdx.x;
    const int m0 = blockIdx.y * MT;
    const int n0 = blockIdx.x * NT;
    const int z = blockIdx.z;
    const uint32_t dyn_u32 = smem_u32(dynsm);

    const __nv_bfloat16* Ahg = (z ? Ah1 : Ah0) + (size_t)m0 * KPAD;
    const __nv_bfloat16* Alg = (z ? Al1 : Al0) + (size_t)m0 * KPAD;
    const __nv_bfloat16* Bhg = (z ? Bh1 : Bh0) + (size_t)n0 * KPAD;
    const __nv_bfloat16* Blg = (z ? Bl1 : Bl0) + (size_t)n0 * KPAD;
    float* Yf = z ? Yf1 : Yf0;
    __nv_bfloat16* YTh = z ? YTh1 : YTh0;
    __nv_bfloat16* YTl = z ? YTl1 : YTl0;

    auto load_chunk = [&](int ck, uint32_t stg) {
        const int kb = ck * 64;
#pragma unroll
        for (int i = 0; i < 4; i++) {
            int idx = t + i * 256;
            int row = idx >> 3, seg = idx & 7;
            size_t go = (size_t)row * KPAD + kb + seg * 8;
            uint32_t so = sw128((uint32_t)(row * 128 + seg * 16));
            CP_ASYNC16(dyn_u32 + stg + ST_AH + so, Ahg + go);
            CP_ASYNC16(dyn_u32 + stg + ST_AL + so, Alg + go);
        }
#pragma unroll
        for (int i = 0; i < 8; i++) {
            int idx = t + i * 256;
            int row = idx >> 3, seg = idx & 7;
            size_t go = (size_t)row * KPAD + kb + seg * 8;
            uint32_t so = sw128((uint32_t)(row * 128 + seg * 16));
            CP_ASYNC16(dyn_u32 + stg + ST_BH + so, Bhg + go);
            CP_ASYNC16(dyn_u32 + stg + ST_BL + so, Blg + go);
        }
        CP_COMMIT();
    };

#if HAS_TCGEN05
    __shared__ uint32_t s_tmem;
    __shared__ __align__(8) uint64_t s_mbar[2];
    const uint32_t mbar0 = smem_u32(&s_mbar[0]);
    const uint32_t mbar1 = smem_u32(&s_mbar[1]);

    if ((t >> 5) == 0) TC_ALLOC(smem_u32(&s_tmem), 256);
    if (t == 0) {
        MBAR_INIT(mbar0, 1);
        MBAR_INIT(mbar1, 1);
    }
    __syncthreads();
    const uint32_t tmem = s_tmem;

    load_chunk(0, 0);
    load_chunk(1, STAGE_SZ);

    for (int k = 0; k < NCHUNK; k++) {
        const int s = k & 1;
        const uint32_t stage = s ? STAGE_SZ : 0;
        if (k == NCHUNK - 1) { CP_WAIT0(); } else { CP_WAIT1(); }
        __syncthreads();
        if ((t >> 5) == 0) {
            FENCE_ASYNC();
            if (elect_one()) {
                uint64_t dAh = make_desc(dyn_u32 + stage + ST_AH);
                uint64_t dAl = make_desc(dyn_u32 + stage + ST_AL);
                uint64_t dBh = make_desc(dyn_u32 + stage + ST_BH);
                uint64_t dBl = make_desc(dyn_u32 + stage + ST_BL);
#pragma unroll
                for (int ks = 0; ks < 4; ks++)
                    mma_f16_ss(tmem, dAh + ks * 2, dBh + ks * 2, MMA_IDESC,
                               (k != 0 || ks != 0) ? 1u : 0u);
#pragma unroll
                for (int ks = 0; ks < 4; ks++)
                    mma_f16_ss(tmem, dAh + ks * 2, dBl + ks * 2, MMA_IDESC, 1u);
#pragma unroll
                for (int ks = 0; ks < 4; ks++)
                    mma_f16_ss(tmem, dAl + ks * 2, dBh + ks * 2, MMA_IDESC, 1u);
                TC_COMMIT(s ? mbar1 : mbar0);
            }
        }
        if (k + 2 < NCHUNK) {
            mbar_wait(s ? mbar1 : mbar0, (k >> 1) & 1);
            load_chunk(k + 2, stage);
        }
    }
    mbar_wait(mbar0, 1);
    mbar_wait(mbar1, 0);
    TC_FENCE_AFTER();
    __syncthreads();

    const bool doT = (YTh != nullptr);
    const int w = t >> 5;
    const int chal = w >> 2;
    const int lane = t & 31;
    const int rl = (w & 3) * 32 + lane;
    const int m = m0 + rl;
    const bool vm = (m < NCOLS);
    __nv_bfloat16* shh = (__nv_bfloat16*)dynsm;
    __nv_bfloat16* shl = shh + 128 * SST;

    for (int cb = 0; cb < 4; cb++) {
        const int c0 = chal * 128 + cb * 32;
        uint32_t regs[32];
        LDTM_X32(regs, tmem + c0);
        TC_WAIT_LD();
#pragma unroll
        for (int j = 0; j < 32; j++) {
            int n = n0 + c0 + j;
            float y = alpha * __uint_as_float(regs[j]);
            bool vn = (n < NNODES);
            if (beta != 0.f && vm && vn) y += beta * Xprev[(size_t)n * NCOLS + m];
            if (vm && vn) Yf[(size_t)n * NCOLS + m] = y;
            if (doT) {
                __nv_bfloat16 h, l;
                split_bf16(y, h, l);
                shh[rl * SST + c0 + j] = h;
                shl[rl * SST + c0 + j] = l;
            }
        }
    }
    if (doT) {
        __syncthreads();
        int r = t >> 1, half = t & 1;
        int m2 = m0 + r;
        if (m2 < NCOLS) {
#pragma unroll
            for (int v = 0; v < 16; v++) {
                int nn = n0 + half * 128 + v * 8;
                int sidx = r * SST + half * 128 + v * 8;
                if (nn + 8 <= NNODES) {
                    *(uint4*)(YTh + (size_t)m2 * KPAD + nn) = *(uint4*)&shh[sidx];
                    *(uint4*)(YTl + (size_t)m2 * KPAD + nn) = *(uint4*)&shl[sidx];
                } else {
                    for (int e = 0; e < 8; e++)
                        if (nn + e < NNODES) {
                            YTh[(size_t)m2 * KPAD + nn + e] = shh[sidx + e];
                            YTl[(size_t)m2 * KPAD + nn + e] = shl[sidx + e];
                        }
                }
            }
        }
    }
    __syncthreads();
    if (t == 0) { MBAR_INVAL(mbar0); MBAR_INVAL(mbar1); }
    __syncthreads();
    if ((t >> 5) == 0) {
        TC_RELINQ();
        TC_DEALLOC(tmem, 256);
    }
#else
    const int lane = t & 31;
    const int warp = t >> 5;
    const int wm = warp & 1;
    const int wn = warp >> 1;
    const int lg = lane >> 3, lr = lane & 7;

    float acc[4][8][4];
#pragma unroll
    for (int i = 0; i < 4; i++)
#pragma unroll
        for (int j = 0; j < 8; j++)
#pragma unroll
            for (int e = 0; e < 4; e++) acc[i][j][e] = 0.f;

    for (int chunk = 0; chunk < NCHUNK; chunk++) {
        load_chunk(chunk, 0);
        CP_WAIT0();
        __syncthreads();
#pragma unroll
        for (int ks = 0; ks < 4; ks++) {
            uint32_t ah[4][4], al[4][4];
#pragma unroll
            for (int am = 0; am < 4; am++) {
                int row = wm * 64 + am * 16 + (lg & 1) * 8 + lr;
                int koff = ks * 32 + (lg >> 1) * 16;
                uint32_t so = sw128((uint32_t)(row * 128 + koff));
                ldm4(ah[am], dyn_u32 + ST_AH + so);
                ldm4(al[am], dyn_u32 + ST_AL + so);
            }
            uint32_t bh[4][4], bl[4][4];
#pragma unroll
            for (int p = 0; p < 4; p++) {
                int row = wn * 64 + p * 16 + (lg >> 1) * 8 + lr;
                int koff = ks * 32 + (lg & 1) * 16;
                uint32_t so = sw128((uint32_t)(row * 128 + koff));
                ldm4(bh[p], dyn_u32 + ST_BH + so);
                ldm4(bl[p], dyn_u32 + ST_BL + so);
            }
#pragma unroll
            for (int am = 0; am < 4; am++)
#pragma unroll
                for (int an = 0; an < 8; an++) {
                    int p = an >> 1, h = (an & 1) * 2;
                    mma16816(acc[am][an], ah[am], bh[p][h], bh[p][h + 1]);
                    mma16816(acc[am][an], ah[am], bl[p][h], bl[p][h + 1]);
                    mma16816(acc[am][an], al[am], bh[p][h], bh[p][h + 1]);
                }
        }
        __syncthreads();
    }

    const bool doT = (YTh != nullptr);
#pragma unroll
    for (int am = 0; am < 4; am++) {
#pragma unroll
        for (int an = 0; an < 8; an++) {
            int mrow = m0 + wm * 64 + am * 16 + (lane >> 2);
            int ncol = n0 + wn * 64 + an * 8 + (lane & 3) * 2;
#pragma unroll
            for (int h = 0; h < 2; h++) {
                int m = mrow + h * 8;
                if (m >= NCOLS) continue;
#pragma unroll
                for (int e = 0; e < 2; e++) {
                    int n = ncol + e;
                    if (n >= NNODES) continue;
                    float y = alpha * acc[am][an][h * 2 + e];
                    if (beta != 0.f) y += beta * Xprev[(size_t)n * NCOLS + m];
                    Yf[(size_t)n * NCOLS + m] = y;
                    if (doT) {
                        __nv_bfloat16 hh, ll;
                        split_bf16(y, hh, ll);
                        YTh[(size_t)m * KPAD + n] = hh;
                        YTl[(size_t)m * KPAD + n] = ll;
                    }
                }
            }
        }
    }
#endif
}

// ---------------- gate projection (R4 SIMT) ----------------
__global__ void k_proj_gate(const float* __restrict__ Wg, const float* __restrict__ bg,
                            const float* __restrict__ hx,
                            const float* __restrict__ X0, const float* __restrict__ X1a,
                            const float* __restrict__ X2a, const float* __restrict__ X1b,
                            const float* __restrict__ X2b,
                            float* __restrict__ X0w,
                            __nv_bfloat16* __restrict__ X0Th, __nv_bfloat16* __restrict__ X0Tl,
                            float* __restrict__ ubuf) {
    __shared__ float sx[5][NCOLS];
    int n = blockIdx.x;
    const float* mats[5] = {X0, X1a, X2a, X1b, X2b};
    for (int tt = threadIdx.x; tt < 5 * NCOLS; tt += blockDim.x) {
        int m = tt / NCOLS;
        int idx = tt - m * NCOLS;
        sx[m][idx] = mats[m][(size_t)n * NCOLS + idx];
    }
    __syncthreads();

    int o = threadIdx.x;
    float acc[BATCH];
#pragma unroll
    for (int b = 0; b < BATCH; b++) acc[b] = bg[o];
    for (int c = 0; c < CCH; c++) {
#pragma unroll
        for (int m = 0; m < 5; m++) {
            float w = Wg[(size_t)(c * 5 + m) * NGATE + o];
#pragma unroll
            for (int b = 0; b < BATCH; b++) acc[b] += sx[m][c * 16 + b] * w;
        }
    }
#pragma unroll
    for (int b = 0; b < BATCH; b++) {
        float s = 1.f / (1.f + __expf(-acc[b]));
        if (o < NUNITS) {
            float h = hx[(size_t)b * HXSZ + n * NUNITS + o];
            float rh = s * h;
            X0w[(size_t)n * NCOLS + (NFEAT + o) * 16 + b] = rh;
            int rr = (NFEAT + o) * 16 + b;
            __nv_bfloat16 hi, lo;
            split_bf16(rh, hi, lo);
            X0Th[(size_t)rr * KPAD + n] = hi;
            X0Tl[(size_t)rr * KPAD + n] = lo;
        } else {
            ubuf[(size_t)b * HXSZ + n * NUNITS + (o - NUNITS)] = s;
        }
    }
}

// ---------------- cand projection + GRU combine (R4 SIMT) ----------------
__global__ void k_proj_cand(const float* __restrict__ Wc, const float* __restrict__ bc,
                            const float* __restrict__ hx, const float* __restrict__ ubuf,
                            const float* __restrict__ X0, const float* __restrict__ X1a,
                            const float* __restrict__ X2a, const float* __restrict__ X1b,
                            const float* __restrict__ X2b,
                            float* __restrict__ out) {
    __shared__ float sx[5][NCOLS];
    int n = blockIdx.x;
    const float* mats[5] = {X0, X1a, X2a, X1b, X2b};
    for (int tt = threadIdx.x; tt < 5 * NCOLS; tt += blockDim.x) {
        int m = tt / NCOLS;
        int idx = tt - m * NCOLS;
        sx[m][idx] = mats[m][(size_t)n * NCOLS + idx];
    }
    __syncthreads();

    int o = threadIdx.x;
    float acc[BATCH];
#pragma unroll
    for (int b = 0; b < BATCH; b++) acc[b] = bc[o];
    for (int c = 0; c < CCH; c++) {
#pragma unroll
        for (int m = 0; m < 5; m++) {
            float w = Wc[(size_t)(c * 5 + m) * NUNITS + o];
#pragma unroll
            for (int b = 0; b < BATCH; b++) acc[b] += sx[m][c * 16 + b] * w;
        }
    }
#pragma unroll
    for (int b = 0; b < BATCH; b++) {
        float cc = tanhf(acc[b]);
        size_t i = (size_t)b * HXSZ + n * NUNITS + o;
        float u = ubuf[i];
        float h = hx[i];
        out[i] = u * h + (1.f - u) * cc;
    }
}

// ---------------- launch ----------------
extern "C" void kernel_launch(void* const* d_in, const int* in_sizes, int n_in,
                              void* d_out, int out_size) {
    const float* inputs = (const float*)d_in[0];
    const float* hx     = (const float*)d_in[1];
    const float* adj    = (const float*)d_in[2];
    const float* Wg     = (const float*)d_in[3];
    const float* bg     = (const float*)d_in[4];
    const float* Wc     = (const float*)d_in[5];
    const float* bc     = (const float*)d_in[6];
    float* out = (float*)d_out;

    __nv_bfloat16 *S0h, *S0l, *S1h, *S1l, *X0Th, *X0Tl, *X1aTh, *X1aTl, *X1bTh, *X1bTl;
    float *X0, *X1a, *X2a, *X1b, *X2b, *invdr, *dcol, *invdc, *ubuf;
    cudaGetSymbolAddress((void**)&S0h, g_S0h);
    cudaGetSymbolAddress((void**)&S0l, g_S0l);
    cudaGetSymbolAddress((void**)&S1h, g_S1h);
    cudaGetSymbolAddress((void**)&S1l, g_S1l);
    cudaGetSymbolAddress((void**)&X0Th, g_X0Th);
    cudaGetSymbolAddress((void**)&X0Tl, g_X0Tl);
    cudaGetSymbolAddress((void**)&X1aTh, g_X1aTh);
    cudaGetSymbolAddress((void**)&X1aTl, g_X1aTl);
    cudaGetSymbolAddress((void**)&X1bTh, g_X1bTh);
    cudaGetSymbolAddress((void**)&X1bTl, g_X1bTl);
    cudaGetSymbolAddress((void**)&X0, g_X0);
    cudaGetSymbolAddress((void**)&X1a, g_X1a);
    cudaGetSymbolAddress((void**)&X2a, g_X2a);
    cudaGetSymbolAddress((void**)&X1b, g_X1b);
    cudaGetSymbolAddress((void**)&X2b, g_X2b);
    cudaGetSymbolAddress((void**)&invdr, g_invdr);
    cudaGetSymbolAddress((void**)&dcol, g_dcol);
    cudaGetSymbolAddress((void**)&invdc, g_invdc);
    cudaGetSymbolAddress((void**)&ubuf, g_u);

    cudaFuncSetAttribute(k_gemm_tc, cudaFuncAttributeMaxDynamicSharedMemorySize, SMEM_DYN);
    cudaFuncSetAttribute(k_buildX0_all, cudaFuncAttributeMaxDynamicSharedMemorySize, 69632);

    k_rowsum<<<NNODES, 256>>>(adj, invdr);
    k_zero_dcol<<<(NNODES + 255) / 256, 256>>>(dcol);
    {
        dim3 g((NNODES + 255) / 256, 24);
        k_colsum_part<<<g, 256>>>(adj, dcol);
    }
    k_invert_dcol<<<(NNODES + 255) / 256, 256>>>(dcol, invdc);

    {
        dim3 g(NPADS / 32, KPAD / 32);
        k_buildS0_split<<<g, dim3(32, 8)>>>(adj, invdr, S0h, S0l);
    }
    k_buildS1_splitv<<<(NPADS * 376 + 255) / 256, 256>>>(adj, invdc, S1h, S1l);

    k_buildX0_all<<<KPAD / 16, 256, 69632>>>(inputs, hx, X0, X0Th, X0Tl);
    k_zero_padsT6<<<(PADELEMS + 255) / 256, 256>>>(X1aTh, X1aTl, X1bTh, X1bTl, X0Th, X0Tl);

    dim3 ggrid(NPADS / NT, MPAD / MT, 2);  // 12 x 9 x 2

    // gconv 1 (gate)
    k_gemm_tc<<<ggrid, 256, SMEM_DYN>>>(X0Th, X0Tl, X0Th, X0Tl,
                                        S0h, S0l, S1h, S1l,
                                        nullptr, X1a, X1b,
                                        X1aTh, X1aTl, X1bTh, X1bTl, 1.f, 0.f);
    k_gemm_tc<<<ggrid, 256, SMEM_DYN>>>(X1aTh, X1aTl, X1bTh, X1bTl,
                                        S0h, S0l, S1h, S1l,
                                        X0, X2a, X2b,
                                        nullptr, nullptr, nullptr, nullptr, 2.f, -1.f);

    k_proj_gate<<<NNODES, 128>>>(Wg, bg, hx, X0, X1a, X2a, X1b, X2b, X0, X0Th, X0Tl, ubuf);

    // gconv 2 (candidate)
    k_gemm_tc<<<ggrid, 256, SMEM_DYN>>>(X0Th, X0Tl, X0Th, X0Tl,
                                        S0h, S0l, S1h, S1l,
                                        nullptr, X1a, X1b,
                                        X1aTh, X1aTl, X1bTh, X1bTl, 1.f, 0.f);
    k_gemm_tc<<<ggrid, 256, SMEM_DYN>>>(X1aTh, X1aTl, X1bTh, X1bTl,
                                        S0h, S0l, S1h, S1l,
                                        X0, X2a, X2b,
                                        nullptr, nullptr, nullptr, nullptr, 2.f, -1.f);

    k_proj_cand<<<NNODES, 64>>>(Wc, bc, hx, ubuf, X0, X1a, X2a, X1b, X2b, out);
}